// round 15
// baseline (speedup 1.0000x reference)
#include <cuda_runtime.h>
#include <cuda_bf16.h>
#include <cstdint>

// ---------------------------------------------------------------------------
// out[b,v] = h2[b] . emb[v] + c[b]   (rank-16 reduction of the final GEMM)
// k1 algebra (R14): score via folded Wf=(wq+wk)@fc0_w; sg/sl via pooled me.
// k2: R6 core + PDL wait, now __launch_bounds__(256,3) -> 3 blocks/SM
//     (shorter tail wave, 24 warps/SM latency cover). Lean epilogue keeps
//     regs <= 85 without spills (R4 precedent).
// ---------------------------------------------------------------------------

#define VOCAB 128000
#define EMB   32
#define HALF  16
#define BATCH 1024
#define SEQ   50

__device__ __align__(16) float g_h2[BATCH * HALF];
__device__ __align__(16) float g_c[BATCH];

typedef unsigned long long ull;

__device__ __forceinline__ ull pk2(float lo, float hi) {
    ull r; asm("mov.b64 %0, {%1, %2};" : "=l"(r) : "f"(lo), "f"(hi)); return r;
}
__device__ __forceinline__ void unpk2(ull v, float& lo, float& hi) {
    asm("mov.b64 {%0, %1}, %2;" : "=f"(lo), "=f"(hi) : "l"(v));
}
__device__ __forceinline__ ull mul2(ull a, ull b) {
    ull d; asm("mul.rn.f32x2 %0, %1, %2;" : "=l"(d) : "l"(a), "l"(b)); return d;
}
__device__ __forceinline__ ull fma2(ull a, ull b, ull c) {
    ull d; asm("fma.rn.f32x2 %0, %1, %2, %3;" : "=l"(d) : "l"(a), "l"(b), "l"(c)); return d;
}
__device__ __forceinline__ ull add2(ull a, ull b) {
    ull d; asm("add.rn.f32x2 %0, %1, %2;" : "=l"(d) : "l"(a), "l"(b)); return d;
}
__device__ __forceinline__ float tanh_fast(float x) {
    float y; asm("tanh.approx.f32 %0, %1;" : "=f"(y) : "f"(x)); return y;
}

// ---------------------------------------------------------------------------
// Kernel 1 (R14): 4 batch rows/block, 2 warps/row, lane = seq position.
// ---------------------------------------------------------------------------
#define K1_ROWS 4

__global__ void __launch_bounds__(256) k1_attend(
    const int*   __restrict__ text,
    const float* __restrict__ emb,
    const float* __restrict__ fc0_w,
    const float* __restrict__ fc0_b,
    const float* __restrict__ wq,
    const float* __restrict__ wk,
    const float* __restrict__ av,
    const float* __restrict__ out_w,
    const float* __restrict__ out_b)
{
    __shared__ __align__(16) float s_fc0w[EMB * HALF];
    __shared__ float s_W[EMB * EMB];
    __shared__ __align__(16) float s_Wf[EMB * HALF];
    __shared__ float s_cvec[EMB];
    __shared__ float s_outw[EMB * 65];
    __shared__ float s_av[EMB], s_fc0b[EMB], s_outb[EMB];
    __shared__ float s_sc[K1_ROWS][SEQ];
    __shared__ __align__(16) ull s_part[K1_ROWS][2][8];
    __shared__ float s_wsum[K1_ROWS][2];
    __shared__ __align__(16) ull s_me49[K1_ROWS][8];
    __shared__ float s_m49[K1_ROWS];
    __shared__ float s_vec[K1_ROWS][2][EMB];

    const int tid = threadIdx.x;
    const int b0  = blockIdx.x * K1_ROWS;

    const int w    = tid >> 5;
    const int lane = tid & 31;
    const int row  = w >> 1;
    const int sidx = ((w & 1) << 5) + lane;
    const bool act = sidx < SEQ;

    const int tok = __ldg(text + (size_t)(b0 + row) * SEQ + (act ? sidx : 0));
    const bool valid = act && (tok != 0) && (tok != 1);
    const float msk = valid ? 1.0f : 0.0f;
    const float4* er = reinterpret_cast<const float4*>(emb + (size_t)tok * HALF);
    float4 q0 = __ldg(er + 0), q1 = __ldg(er + 1), q2 = __ldg(er + 2), q3 = __ldg(er + 3);

    for (int i = tid; i < EMB * HALF; i += 256) s_fc0w[i] = fc0_w[i];
    for (int i = tid; i < EMB * EMB; i += 256)  s_W[i] = wq[i] + wk[i];
    for (int i = tid; i < EMB * 2 * EMB; i += 256) {
        int r = i >> 6, c = i & 63;
        s_outw[r * 65 + c] = out_w[i];
    }
    if (tid < EMB) { s_av[tid] = av[tid]; s_fc0b[tid] = fc0_b[tid]; s_outb[tid] = out_b[tid]; }
    __syncthreads();

    for (int i = tid; i < EMB * HALF; i += 256) {
        const int e = i >> 4, h = i & 15;
        float acc = 0.0f;
#pragma unroll
        for (int j = 0; j < EMB; j++) acc += s_W[e * EMB + j] * s_fc0w[j * HALF + h];
        s_Wf[i] = acc;
    }
    if (tid < EMB) {
        float acc = 0.0f;
#pragma unroll
        for (int j = 0; j < EMB; j++) acc += s_W[tid * EMB + j] * s_fc0b[j];
        s_cvec[tid] = acc;
    }
    __syncthreads();

    ull me[8];
    me[0] = pk2(q0.x, q0.y); me[1] = pk2(q0.z, q0.w);
    me[2] = pk2(q1.x, q1.y); me[3] = pk2(q1.z, q1.w);
    me[4] = pk2(q2.x, q2.y); me[5] = pk2(q2.z, q2.w);
    me[6] = pk2(q3.x, q3.y); me[7] = pk2(q3.z, q3.w);

    float score = 0.0f;
#pragma unroll 4
    for (int e = 0; e < EMB; e++) {
        const ulonglong2* wr = reinterpret_cast<const ulonglong2*>(s_Wf + e * HALF);
        ulonglong2 u0 = wr[0], u1 = wr[1], u2 = wr[2], u3 = wr[3];
        ull a0 = mul2(me[0], u0.x); ull a1 = mul2(me[1], u0.y);
        a0 = fma2(me[2], u1.x, a0); a1 = fma2(me[3], u1.y, a1);
        a0 = fma2(me[4], u2.x, a0); a1 = fma2(me[5], u2.y, a1);
        a0 = fma2(me[6], u3.x, a0); a1 = fma2(me[7], u3.y, a1);
        a0 = add2(a0, a1);
        float lo, hi; unpk2(a0, lo, hi);
        score += tanh_fast(lo + hi + s_cvec[e]) * s_av[e];
    }
    if (act) s_sc[row][sidx] = valid ? score : -1000000000.0f;
    __syncthreads();

    if ((w & 1) == 0) {
        const int e = lane;
        float sc0 = s_sc[row][e];
        float sc1 = (e < SEQ - 32) ? s_sc[row][e + 32] : -3.4e38f;
        float m = fmaxf(sc0, sc1);
#pragma unroll
        for (int o = 16; o > 0; o >>= 1) m = fmaxf(m, __shfl_xor_sync(0xffffffffu, m, o));
        float ex0 = __expf(sc0 - m);
        float ex1 = (e < SEQ - 32) ? __expf(sc1 - m) : 0.0f;
        float ssum = ex0 + ex1;
#pragma unroll
        for (int o = 16; o > 0; o >>= 1) ssum += __shfl_xor_sync(0xffffffffu, ssum, o);
        const float inv = 1.0f / ssum;
        s_sc[row][e] = ex0 * inv;
        if (e < SEQ - 32) s_sc[row][e + 32] = ex1 * inv;
    }
    __syncthreads();

    {
        float wv = 0.0f;
        if (act) wv = s_sc[row][sidx] * msk;
        ull wp = pk2(wv, wv);
        ull wme[8];
#pragma unroll
        for (int p = 0; p < 8; p++) wme[p] = mul2(wp, me[p]);
        float ws = wv;
#pragma unroll
        for (int o = 16; o > 0; o >>= 1) {
#pragma unroll
            for (int p = 0; p < 8; p++)
                wme[p] = add2(wme[p], __shfl_xor_sync(0xffffffffu, wme[p], o));
            ws += __shfl_xor_sync(0xffffffffu, ws, o);
        }
        if (lane == 0) {
#pragma unroll
            for (int p = 0; p < 8; p++) s_part[row][w & 1][p] = wme[p];
            s_wsum[row][w & 1] = ws;
        }
        if (act && sidx == SEQ - 1) {
            ull mm = pk2(msk, msk);
#pragma unroll
            for (int p = 0; p < 8; p++) s_me49[row][p] = mul2(mm, me[p]);
            s_m49[row] = msk;
        }
    }
    __syncthreads();

    if ((w & 1) == 0) {
        const int e = lane;
        ull mg[8];
        const ull* p0 = s_part[row][0];
        const ull* p1 = s_part[row][1];
#pragma unroll
        for (int p = 0; p < 8; p++) mg[p] = add2(p0[p], p1[p]);
        const float wsum = s_wsum[row][0] + s_wsum[row][1];

        const ulonglong2* fr = reinterpret_cast<const ulonglong2*>(s_fc0w + e * HALF);
        ulonglong2 f0 = fr[0], f1 = fr[1], f2 = fr[2], f3 = fr[3];

        ull a0 = mul2(mg[0], f0.x); ull a1 = mul2(mg[1], f0.y);
        a0 = fma2(mg[2], f1.x, a0); a1 = fma2(mg[3], f1.y, a1);
        a0 = fma2(mg[4], f2.x, a0); a1 = fma2(mg[5], f2.y, a1);
        a0 = fma2(mg[6], f3.x, a0); a1 = fma2(mg[7], f3.y, a1);
        a0 = add2(a0, a1);
        float lo, hi; unpk2(a0, lo, hi);
        const float sg = lo + hi + s_fc0b[e] * wsum;

        const ull* m9 = s_me49[row];
        ull b0v = mul2(m9[0], f0.x); ull b1v = mul2(m9[1], f0.y);
        b0v = fma2(m9[2], f1.x, b0v); b1v = fma2(m9[3], f1.y, b1v);
        b0v = fma2(m9[4], f2.x, b0v); b1v = fma2(m9[5], f2.y, b1v);
        b0v = fma2(m9[6], f3.x, b0v); b1v = fma2(m9[7], f3.y, b1v);
        b0v = add2(b0v, b1v);
        float lo2, hi2; unpk2(b0v, lo2, hi2);
        const float sl = lo2 + hi2 + s_fc0b[e] * s_m49[row];

        s_vec[row][0][e] = sg;
        s_vec[row][1][e] = sl;
        __syncwarp();

        float hid = s_outb[e];
        const float* owr = s_outw + e * 65;
#pragma unroll
        for (int j = 0; j < EMB; j++)
            hid += s_vec[row][0][j] * owr[j] + s_vec[row][1][j] * owr[EMB + j];

        s_vec[row][0][e] = hid;
        __syncwarp();
        if (e < HALF) {
            float a = 0.0f;
#pragma unroll
            for (int j = 0; j < EMB; j++) a += s_vec[row][0][j] * s_fc0w[j * HALF + e];
            g_h2[(b0 + row) * HALF + e] = a;
        }
        float cp = hid * s_fc0b[e];
#pragma unroll
        for (int o = 16; o > 0; o >>= 1) cp += __shfl_xor_sync(0xffffffffu, cp, o);
        if (e == 0) g_c[b0 + row] = cp;
    }

    asm volatile("griddepcontrol.launch_dependents;" ::: "memory");
}

// ---------------------------------------------------------------------------
// Kernel 2: R6 core + PDL wait, 3 blocks/SM (reg cap 85, lean epilogue).
// ---------------------------------------------------------------------------
#define K2_THREADS 256
#define K2_BT      128
#define K2_TV      4

__global__ void __launch_bounds__(K2_THREADS, 3) k2_score(
    const float* __restrict__ emb,
    float*       __restrict__ out)
{
    __shared__ float s_h2[K2_BT * HALF];
    __shared__ float2 s_c2[K2_BT];

    const int tid = threadIdx.x;
    const int b0  = blockIdx.y * K2_BT;

    const size_t v0 = ((size_t)blockIdx.x * K2_THREADS + tid) * K2_TV;

    // emb gather before the PDL wait (overlaps k1 tail)
    ull ev[K2_TV][8];
#pragma unroll
    for (int v = 0; v < K2_TV; v++) {
        const ulonglong2* ep = reinterpret_cast<const ulonglong2*>(emb + (v0 + v) * HALF);
        ulonglong2 u0 = __ldg(ep + 0), u1 = __ldg(ep + 1),
                   u2 = __ldg(ep + 2), u3 = __ldg(ep + 3);
        ev[v][0] = u0.x; ev[v][1] = u0.y; ev[v][2] = u1.x; ev[v][3] = u1.y;
        ev[v][4] = u2.x; ev[v][5] = u2.y; ev[v][6] = u3.x; ev[v][7] = u3.y;
    }

    asm volatile("griddepcontrol.wait;" ::: "memory");

    for (int i = tid; i < K2_BT * HALF / 4; i += K2_THREADS)
        reinterpret_cast<float4*>(s_h2)[i] =
            reinterpret_cast<const float4*>(g_h2 + b0 * HALF)[i];
    if (tid < K2_BT) s_c2[tid] = make_float2(g_c[b0 + tid], 0.0f);
    __syncthreads();

    const ull* c2p = reinterpret_cast<const ull*>(s_c2);
    float4* optr = reinterpret_cast<float4*>(out + (size_t)b0 * VOCAB + v0);
    const size_t row4 = (size_t)VOCAB / 4;

#pragma unroll 1
    for (int bb = 0; bb < K2_BT; bb++) {
        const ulonglong2* hq = reinterpret_cast<const ulonglong2*>(s_h2 + bb * HALF);
        ulonglong2 hA = hq[0], hB = hq[1], hC = hq[2], hD = hq[3];
        const ull c20 = c2p[bb];

        ull a0 = fma2(ev[0][0], hA.x, c20);
        ull a1 = fma2(ev[1][0], hA.x, c20);
        ull a2 = fma2(ev[2][0], hA.x, c20);
        ull a3 = fma2(ev[3][0], hA.x, c20);
        a0 = fma2(ev[0][1], hA.y, a0); a1 = fma2(ev[1][1], hA.y, a1);
        a2 = fma2(ev[2][1], hA.y, a2); a3 = fma2(ev[3][1], hA.y, a3);
        a0 = fma2(ev[0][2], hB.x, a0); a1 = fma2(ev[1][2], hB.x, a1);
        a2 = fma2(ev[2][2], hB.x, a2); a3 = fma2(ev[3][2], hB.x, a3);
        a0 = fma2(ev[0][3], hB.y, a0); a1 = fma2(ev[1][3], hB.y, a1);
        a2 = fma2(ev[2][3], hB.y, a2); a3 = fma2(ev[3][3], hB.y, a3);
        a0 = fma2(ev[0][4], hC.x, a0); a1 = fma2(ev[1][4], hC.x, a1);
        a2 = fma2(ev[2][4], hC.x, a2); a3 = fma2(ev[3][4], hC.x, a3);
        a0 = fma2(ev[0][5], hC.y, a0); a1 = fma2(ev[1][5], hC.y, a1);
        a2 = fma2(ev[2][5], hC.y, a2); a3 = fma2(ev[3][5], hC.y, a3);
        a0 = fma2(ev[0][6], hD.x, a0); a1 = fma2(ev[1][6], hD.x, a1);
        a2 = fma2(ev[2][6], hD.x, a2); a3 = fma2(ev[3][6], hD.x, a3);
        a0 = fma2(ev[0][7], hD.y, a0); a1 = fma2(ev[1][7], hD.y, a1);
        a2 = fma2(ev[2][7], hD.y, a2); a3 = fma2(ev[3][7], hD.y, a3);

        float l0, h0, l1, h1, l2, h2v, l3, h3;
        unpk2(a0, l0, h0); unpk2(a1, l1, h1);
        unpk2(a2, l2, h2v); unpk2(a3, l3, h3);
        __stcs(optr, make_float4(l0 + h0, l1 + h1, l2 + h2v, l3 + h3));
        optr += row4;
    }
}

// ---------------------------------------------------------------------------
extern "C" void kernel_launch(void* const* d_in, const int* in_sizes, int n_in,
                              void* d_out, int out_size)
{
    const int*   text   = (const int*)  d_in[0];
    const float* emb    = (const float*)d_in[1];
    const float* fc0_w  = (const float*)d_in[2];
    const float* fc0_b  = (const float*)d_in[3];
    const float* att_wq = (const float*)d_in[4];
    const float* att_wk = (const float*)d_in[5];
    const float* att_v  = (const float*)d_in[6];
    const float* out_w  = (const float*)d_in[7];
    const float* out_b  = (const float*)d_in[8];
    float* out = (float*)d_out;

    k1_attend<<<BATCH / K1_ROWS, 256>>>(text, emb, fc0_w, fc0_b,
                                        att_wq, att_wk, att_v, out_w, out_b);

    cudaLaunchConfig_t cfg = {};
    cfg.gridDim  = dim3(VOCAB / (K2_THREADS * K2_TV), BATCH / K2_BT);  // (125, 8)
    cfg.blockDim = dim3(K2_THREADS);
    cfg.dynamicSmemBytes = 0;
    cfg.stream = 0;
    cudaLaunchAttribute attr[1];
    attr[0].id = cudaLaunchAttributeProgrammaticStreamSerialization;
    attr[0].val.programmaticStreamSerializationAllowed = 1;
    cfg.attrs = attr;
    cfg.numAttrs = 1;
    cudaLaunchKernelEx(&cfg, k2_score, emb, out);
}

// round 16
// speedup vs baseline: 1.0906x; 1.0906x over previous
#include <cuda_runtime.h>
#include <cuda_bf16.h>
#include <cstdint>

// ---------------------------------------------------------------------------
// FINAL: best-known combination of all 15 rounds.
// out[b,v] = h2[b] . emb[v] + c[b]   (rank-16 reduction of the final GEMM)
//   h2[b] = hidden[b] @ fc0_w (16),  c[b] = hidden[b] . fc0_b
// k1 (R14 algebra): score via folded Wf=(wq+wk)@fc0_w; sg/sl via pooled me;
//   embedded never materialized.
// k2 (R6 frozen core): TV=4, BT=128, k-packed f32x2, c in acc init, lo+hi
//   epilogue, unroll 1, regs UNCAPPED (92) — the only 99-us configuration.
// PDL: k2 gathers its emb registers before griddepcontrol.wait.
// ---------------------------------------------------------------------------

#define VOCAB 128000
#define EMB   32
#define HALF  16
#define BATCH 1024
#define SEQ   50

__device__ __align__(16) float g_h2[BATCH * HALF];
__device__ __align__(16) float g_c[BATCH];

typedef unsigned long long ull;

__device__ __forceinline__ ull pk2(float lo, float hi) {
    ull r; asm("mov.b64 %0, {%1, %2};" : "=l"(r) : "f"(lo), "f"(hi)); return r;
}
__device__ __forceinline__ void unpk2(ull v, float& lo, float& hi) {
    asm("mov.b64 {%0, %1}, %2;" : "=f"(lo), "=f"(hi) : "l"(v));
}
__device__ __forceinline__ ull mul2(ull a, ull b) {
    ull d; asm("mul.rn.f32x2 %0, %1, %2;" : "=l"(d) : "l"(a), "l"(b)); return d;
}
__device__ __forceinline__ ull fma2(ull a, ull b, ull c) {
    ull d; asm("fma.rn.f32x2 %0, %1, %2, %3;" : "=l"(d) : "l"(a), "l"(b), "l"(c)); return d;
}
__device__ __forceinline__ ull add2(ull a, ull b) {
    ull d; asm("add.rn.f32x2 %0, %1, %2;" : "=l"(d) : "l"(a), "l"(b)); return d;
}
__device__ __forceinline__ float tanh_fast(float x) {
    float y; asm("tanh.approx.f32 %0, %1;" : "=f"(y) : "f"(x)); return y;
}

// ---------------------------------------------------------------------------
// Kernel 1 (R14): 4 batch rows/block, 2 warps/row, lane = seq position.
// ---------------------------------------------------------------------------
#define K1_ROWS 4

__global__ void __launch_bounds__(256) k1_attend(
    const int*   __restrict__ text,
    const float* __restrict__ emb,
    const float* __restrict__ fc0_w,
    const float* __restrict__ fc0_b,
    const float* __restrict__ wq,
    const float* __restrict__ wk,
    const float* __restrict__ av,
    const float* __restrict__ out_w,
    const float* __restrict__ out_b)
{
    __shared__ __align__(16) float s_fc0w[EMB * HALF];
    __shared__ float s_W[EMB * EMB];
    __shared__ __align__(16) float s_Wf[EMB * HALF];
    __shared__ float s_cvec[EMB];
    __shared__ float s_outw[EMB * 65];
    __shared__ float s_av[EMB], s_fc0b[EMB], s_outb[EMB];
    __shared__ float s_sc[K1_ROWS][SEQ];
    __shared__ __align__(16) ull s_part[K1_ROWS][2][8];
    __shared__ float s_wsum[K1_ROWS][2];
    __shared__ __align__(16) ull s_me49[K1_ROWS][8];
    __shared__ float s_m49[K1_ROWS];
    __shared__ float s_vec[K1_ROWS][2][EMB];

    const int tid = threadIdx.x;
    const int b0  = blockIdx.x * K1_ROWS;

    const int w    = tid >> 5;
    const int lane = tid & 31;
    const int row  = w >> 1;
    const int sidx = ((w & 1) << 5) + lane;
    const bool act = sidx < SEQ;

    // ---- issue token + emb gather FIRST ----
    const int tok = __ldg(text + (size_t)(b0 + row) * SEQ + (act ? sidx : 0));
    const bool valid = act && (tok != 0) && (tok != 1);
    const float msk = valid ? 1.0f : 0.0f;
    const float4* er = reinterpret_cast<const float4*>(emb + (size_t)tok * HALF);
    float4 q0 = __ldg(er + 0), q1 = __ldg(er + 1), q2 = __ldg(er + 2), q3 = __ldg(er + 3);

    // ---- stage raw weights (overlaps gathers) ----
    for (int i = tid; i < EMB * HALF; i += 256) s_fc0w[i] = fc0_w[i];
    for (int i = tid; i < EMB * EMB; i += 256)  s_W[i] = wq[i] + wk[i];
    for (int i = tid; i < EMB * 2 * EMB; i += 256) {
        int r = i >> 6, c = i & 63;
        s_outw[r * 65 + c] = out_w[i];
    }
    if (tid < EMB) { s_av[tid] = av[tid]; s_fc0b[tid] = fc0_b[tid]; s_outb[tid] = out_b[tid]; }
    __syncthreads();

    // ---- fold: Wf = W @ fc0w (32x16); cvec = W @ fc0_b ----
    for (int i = tid; i < EMB * HALF; i += 256) {
        const int e = i >> 4, h = i & 15;
        float acc = 0.0f;
#pragma unroll
        for (int j = 0; j < EMB; j++) acc += s_W[e * EMB + j] * s_fc0w[j * HALF + h];
        s_Wf[i] = acc;
    }
    if (tid < EMB) {
        float acc = 0.0f;
#pragma unroll
        for (int j = 0; j < EMB; j++) acc += s_W[tid * EMB + j] * s_fc0b[j];
        s_cvec[tid] = acc;
    }
    __syncthreads();

    ull me[8];
    me[0] = pk2(q0.x, q0.y); me[1] = pk2(q0.z, q0.w);
    me[2] = pk2(q1.x, q1.y); me[3] = pk2(q1.z, q1.w);
    me[4] = pk2(q2.x, q2.y); me[5] = pk2(q2.z, q2.w);
    me[6] = pk2(q3.x, q3.y); me[7] = pk2(q3.z, q3.w);

    // ---- score[sidx] = sum_e tanh(me.Wf[e] + c_e) * av[e] ----
    float score = 0.0f;
#pragma unroll 4
    for (int e = 0; e < EMB; e++) {
        const ulonglong2* wr = reinterpret_cast<const ulonglong2*>(s_Wf + e * HALF);
        ulonglong2 u0 = wr[0], u1 = wr[1], u2 = wr[2], u3 = wr[3];
        ull a0 = mul2(me[0], u0.x); ull a1 = mul2(me[1], u0.y);
        a0 = fma2(me[2], u1.x, a0); a1 = fma2(me[3], u1.y, a1);
        a0 = fma2(me[4], u2.x, a0); a1 = fma2(me[5], u2.y, a1);
        a0 = fma2(me[6], u3.x, a0); a1 = fma2(me[7], u3.y, a1);
        a0 = add2(a0, a1);
        float lo, hi; unpk2(a0, lo, hi);
        score += tanh_fast(lo + hi + s_cvec[e]) * s_av[e];
    }
    if (act) s_sc[row][sidx] = valid ? score : -1000000000.0f;
    __syncthreads();

    // ---- softmax (one warp per row) ----
    if ((w & 1) == 0) {
        const int e = lane;
        float sc0 = s_sc[row][e];
        float sc1 = (e < SEQ - 32) ? s_sc[row][e + 32] : -3.4e38f;
        float m = fmaxf(sc0, sc1);
#pragma unroll
        for (int o = 16; o > 0; o >>= 1) m = fmaxf(m, __shfl_xor_sync(0xffffffffu, m, o));
        float ex0 = __expf(sc0 - m);
        float ex1 = (e < SEQ - 32) ? __expf(sc1 - m) : 0.0f;
        float ssum = ex0 + ex1;
#pragma unroll
        for (int o = 16; o > 0; o >>= 1) ssum += __shfl_xor_sync(0xffffffffu, ssum, o);
        const float inv = 1.0f / ssum;
        s_sc[row][e] = ex0 * inv;
        if (e < SEQ - 32) s_sc[row][e + 32] = ex1 * inv;
    }
    __syncthreads();

    // ---- pooling: butterfly-reduce w_s*me over lanes; me49 capture ----
    {
        float wv = 0.0f;
        if (act) wv = s_sc[row][sidx] * msk;
        ull wp = pk2(wv, wv);
        ull wme[8];
#pragma unroll
        for (int p = 0; p < 8; p++) wme[p] = mul2(wp, me[p]);
        float ws = wv;
#pragma unroll
        for (int o = 16; o > 0; o >>= 1) {
#pragma unroll
            for (int p = 0; p < 8; p++)
                wme[p] = add2(wme[p], __shfl_xor_sync(0xffffffffu, wme[p], o));
            ws += __shfl_xor_sync(0xffffffffu, ws, o);
        }
        if (lane == 0) {
#pragma unroll
            for (int p = 0; p < 8; p++) s_part[row][w & 1][p] = wme[p];
            s_wsum[row][w & 1] = ws;
        }
        if (act && sidx == SEQ - 1) {
            ull mm = pk2(msk, msk);
#pragma unroll
            for (int p = 0; p < 8; p++) s_me49[row][p] = mul2(mm, me[p]);
            s_m49[row] = msk;
        }
    }
    __syncthreads();

    // ---- head (one warp per row, lane = e) ----
    if ((w & 1) == 0) {
        const int e = lane;
        ull mg[8];
        const ull* p0 = s_part[row][0];
        const ull* p1 = s_part[row][1];
#pragma unroll
        for (int p = 0; p < 8; p++) mg[p] = add2(p0[p], p1[p]);
        const float wsum = s_wsum[row][0] + s_wsum[row][1];

        const ulonglong2* fr = reinterpret_cast<const ulonglong2*>(s_fc0w + e * HALF);
        ulonglong2 f0 = fr[0], f1 = fr[1], f2 = fr[2], f3 = fr[3];

        ull a0 = mul2(mg[0], f0.x); ull a1 = mul2(mg[1], f0.y);
        a0 = fma2(mg[2], f1.x, a0); a1 = fma2(mg[3], f1.y, a1);
        a0 = fma2(mg[4], f2.x, a0); a1 = fma2(mg[5], f2.y, a1);
        a0 = fma2(mg[6], f3.x, a0); a1 = fma2(mg[7], f3.y, a1);
        a0 = add2(a0, a1);
        float lo, hi; unpk2(a0, lo, hi);
        const float sg = lo + hi + s_fc0b[e] * wsum;

        const ull* m9 = s_me49[row];
        ull b0v = mul2(m9[0], f0.x); ull b1v = mul2(m9[1], f0.y);
        b0v = fma2(m9[2], f1.x, b0v); b1v = fma2(m9[3], f1.y, b1v);
        b0v = fma2(m9[4], f2.x, b0v); b1v = fma2(m9[5], f2.y, b1v);
        b0v = fma2(m9[6], f3.x, b0v); b1v = fma2(m9[7], f3.y, b1v);
        b0v = add2(b0v, b1v);
        float lo2, hi2; unpk2(b0v, lo2, hi2);
        const float sl = lo2 + hi2 + s_fc0b[e] * s_m49[row];

        s_vec[row][0][e] = sg;
        s_vec[row][1][e] = sl;
        __syncwarp();

        float hid = s_outb[e];
        const float* owr = s_outw + e * 65;
#pragma unroll
        for (int j = 0; j < EMB; j++)
            hid += s_vec[row][0][j] * owr[j] + s_vec[row][1][j] * owr[EMB + j];

        s_vec[row][0][e] = hid;
        __syncwarp();
        if (e < HALF) {
            float a = 0.0f;
#pragma unroll
            for (int j = 0; j < EMB; j++) a += s_vec[row][0][j] * s_fc0w[j * HALF + e];
            g_h2[(b0 + row) * HALF + e] = a;
        }
        float cp = hid * s_fc0b[e];
#pragma unroll
        for (int o = 16; o > 0; o >>= 1) cp += __shfl_xor_sync(0xffffffffu, cp, o);
        if (e == 0) g_c[b0 + row] = cp;
    }

    asm volatile("griddepcontrol.launch_dependents;" ::: "memory");
}

// ---------------------------------------------------------------------------
// Kernel 2 (FROZEN R6 core, uncapped regs): out[b,v] = h2[b].emb[v] + c[b]
// TV=4 k-packed f32x2; per bb: 4 LDS.128 + 1 LDS.64 + 32 FFMA2 + 4 FADD
// + 1 STG.128; unroll 1.
// ---------------------------------------------------------------------------
#define K2_THREADS 256
#define K2_BT      128
#define K2_TV      4

__global__ void __launch_bounds__(K2_THREADS) k2_score(
    const float* __restrict__ emb,
    float*       __restrict__ out)
{
    __shared__ float s_h2[K2_BT * HALF];
    __shared__ float2 s_c2[K2_BT];

    const int tid = threadIdx.x;
    const int b0  = blockIdx.y * K2_BT;

    const size_t v0 = ((size_t)blockIdx.x * K2_THREADS + tid) * K2_TV;

    // emb gather before the PDL wait (overlaps k1 tail)
    ull ev[K2_TV][8];
#pragma unroll
    for (int v = 0; v < K2_TV; v++) {
        const ulonglong2* ep = reinterpret_cast<const ulonglong2*>(emb + (v0 + v) * HALF);
        ulonglong2 u0 = __ldg(ep + 0), u1 = __ldg(ep + 1),
                   u2 = __ldg(ep + 2), u3 = __ldg(ep + 3);
        ev[v][0] = u0.x; ev[v][1] = u0.y; ev[v][2] = u1.x; ev[v][3] = u1.y;
        ev[v][4] = u2.x; ev[v][5] = u2.y; ev[v][6] = u3.x; ev[v][7] = u3.y;
    }

    asm volatile("griddepcontrol.wait;" ::: "memory");

    for (int i = tid; i < K2_BT * HALF / 4; i += K2_THREADS)
        reinterpret_cast<float4*>(s_h2)[i] =
            reinterpret_cast<const float4*>(g_h2 + b0 * HALF)[i];
    if (tid < K2_BT) s_c2[tid] = make_float2(g_c[b0 + tid], 0.0f);
    __syncthreads();

    const ull* c2p = reinterpret_cast<const ull*>(s_c2);
    float4* optr = reinterpret_cast<float4*>(out + (size_t)b0 * VOCAB + v0);
    const size_t row4 = (size_t)VOCAB / 4;

#pragma unroll 1
    for (int bb = 0; bb < K2_BT; bb++) {
        const ulonglong2* hq = reinterpret_cast<const ulonglong2*>(s_h2 + bb * HALF);
        ulonglong2 hA = hq[0], hB = hq[1], hC = hq[2], hD = hq[3];
        const ull c20 = c2p[bb];

        ull a0 = fma2(ev[0][0], hA.x, c20);
        ull a1 = fma2(ev[1][0], hA.x, c20);
        ull a2 = fma2(ev[2][0], hA.x, c20);
        ull a3 = fma2(ev[3][0], hA.x, c20);
        a0 = fma2(ev[0][1], hA.y, a0); a1 = fma2(ev[1][1], hA.y, a1);
        a2 = fma2(ev[2][1], hA.y, a2); a3 = fma2(ev[3][1], hA.y, a3);
        a0 = fma2(ev[0][2], hB.x, a0); a1 = fma2(ev[1][2], hB.x, a1);
        a2 = fma2(ev[2][2], hB.x, a2); a3 = fma2(ev[3][2], hB.x, a3);
        a0 = fma2(ev[0][3], hB.y, a0); a1 = fma2(ev[1][3], hB.y, a1);
        a2 = fma2(ev[2][3], hB.y, a2); a3 = fma2(ev[3][3], hB.y, a3);
        a0 = fma2(ev[0][4], hC.x, a0); a1 = fma2(ev[1][4], hC.x, a1);
        a2 = fma2(ev[2][4], hC.x, a2); a3 = fma2(ev[3][4], hC.x, a3);
        a0 = fma2(ev[0][5], hC.y, a0); a1 = fma2(ev[1][5], hC.y, a1);
        a2 = fma2(ev[2][5], hC.y, a2); a3 = fma2(ev[3][5], hC.y, a3);
        a0 = fma2(ev[0][6], hD.x, a0); a1 = fma2(ev[1][6], hD.x, a1);
        a2 = fma2(ev[2][6], hD.x, a2); a3 = fma2(ev[3][6], hD.x, a3);
        a0 = fma2(ev[0][7], hD.y, a0); a1 = fma2(ev[1][7], hD.y, a1);
        a2 = fma2(ev[2][7], hD.y, a2); a3 = fma2(ev[3][7], hD.y, a3);

        float l0, h0, l1, h1, l2, h2v, l3, h3;
        unpk2(a0, l0, h0); unpk2(a1, l1, h1);
        unpk2(a2, l2, h2v); unpk2(a3, l3, h3);
        __stcs(optr, make_float4(l0 + h0, l1 + h1, l2 + h2v, l3 + h3));
        optr += row4;
    }
}

// ---------------------------------------------------------------------------
extern "C" void kernel_launch(void* const* d_in, const int* in_sizes, int n_in,
                              void* d_out, int out_size)
{
    const int*   text   = (const int*)  d_in[0];
    const float* emb    = (const float*)d_in[1];
    const float* fc0_w  = (const float*)d_in[2];
    const float* fc0_b  = (const float*)d_in[3];
    const float* att_wq = (const float*)d_in[4];
    const float* att_wk = (const float*)d_in[5];
    const float* att_v  = (const float*)d_in[6];
    const float* out_w  = (const float*)d_in[7];
    const float* out_b  = (const float*)d_in[8];
    float* out = (float*)d_out;

    k1_attend<<<BATCH / K1_ROWS, 256>>>(text, emb, fc0_w, fc0_b,
                                        att_wq, att_wk, att_v, out_w, out_b);

    cudaLaunchConfig_t cfg = {};
    cfg.gridDim  = dim3(VOCAB / (K2_THREADS * K2_TV), BATCH / K2_BT);  // (125, 8)
    cfg.blockDim = dim3(K2_THREADS);
    cfg.dynamicSmemBytes = 0;
    cfg.stream = 0;
    cudaLaunchAttribute attr[1];
    attr[0].id = cudaLaunchAttributeProgrammaticStreamSerialization;
    attr[0].val.programmaticStreamSerializationAllowed = 1;
    cfg.attrs = attr;
    cfg.numAttrs = 1;
    cudaLaunchKernelEx(&cfg, k2_score, emb, out);
}